// round 5
// baseline (speedup 1.0000x reference)
#include <cuda_runtime.h>
#include <cuda_bf16.h>

// ---------------------------------------------------------------------------
// PQLinear: out[b,s,o] = sum_i x[b,s,i] * wq[o,i] + bias[o]
//   wq[o,i] = codebook[argmin_k ||w[o, g*8:g*8+8]/rs[o] - cb[k]||^2][i%8] * rs[o]
// Shapes: x [4,1024,2048] f32, weight [2048,2048] f32, codebook [256,8] f32,
//         row_scale [2048,1] f32, bias [2048] f32, out [4,1024,2048] f32.
// ---------------------------------------------------------------------------

#define ODIM 2048
#define IDIM 2048
#define MDIM 4096            // B*S
#define KCB  256             // codewords
#define DSUB 8               // subvector dim
#define NGROUPS ((ODIM * IDIM) / DSUB)   // 524288
#define GPR_SHIFT 8          // groups per row = IDIM/DSUB = 256 = 1<<8

// Dequantized weight scratch (16 MB). Device global => no allocation.
__device__ float g_wq[ODIM * IDIM];

// ---------------------------------------------------------------------------
// Kernel 1: PQ quantize + dequantize weight into g_wq.
// One thread per 8-dim group. Codebook (8 KB) + codeword norms in SMEM.
// Distance: d_k = ||c_k||^2 - 2 * g . c_k   (argmin-equivalent; drop ||g||^2)
// ---------------------------------------------------------------------------
__global__ __launch_bounds__(256)
void pq_quant_kernel(const float* __restrict__ w,
                     const float* __restrict__ cb,
                     const float* __restrict__ rs) {
    __shared__ float4 s_cb[KCB * 2];   // 256 codewords x 8 floats
    __shared__ float  s_cn[KCB];       // ||c_k||^2

    const int tid = threadIdx.x;
    const float4* cb4 = reinterpret_cast<const float4*>(cb);
    for (int i = tid; i < KCB * 2; i += 256) s_cb[i] = cb4[i];
    __syncthreads();
    for (int i = tid; i < KCB; i += 256) {
        float4 a = s_cb[2 * i], b = s_cb[2 * i + 1];
        s_cn[i] = a.x * a.x + a.y * a.y + a.z * a.z + a.w * a.w +
                  b.x * b.x + b.y * b.y + b.z * b.z + b.w * b.w;
    }
    __syncthreads();

    const int g = blockIdx.x * 256 + tid;          // group id (grid is exact)
    const int row = g >> GPR_SHIFT;                // weight row o
    const float scale = rs[row];

    const float4* w4 = reinterpret_cast<const float4*>(w);
    float4 w0 = w4[2 * g], w1 = w4[2 * g + 1];
    float gv0 = w0.x / scale, gv1 = w0.y / scale, gv2 = w0.z / scale, gv3 = w0.w / scale;
    float gv4 = w1.x / scale, gv5 = w1.y / scale, gv6 = w1.z / scale, gv7 = w1.w / scale;

    float best = 3.402823466e38f;
    int bi = 0;
#pragma unroll 8
    for (int k = 0; k < KCB; ++k) {
        float4 c0 = s_cb[2 * k], c1 = s_cb[2 * k + 1];
        float dot = gv0 * c0.x;
        dot = fmaf(gv1, c0.y, dot);
        dot = fmaf(gv2, c0.z, dot);
        dot = fmaf(gv3, c0.w, dot);
        dot = fmaf(gv4, c1.x, dot);
        dot = fmaf(gv5, c1.y, dot);
        dot = fmaf(gv6, c1.z, dot);
        dot = fmaf(gv7, c1.w, dot);
        float d = fmaf(-2.0f, dot, s_cn[k]);
        if (d < best) { best = d; bi = k; }       // strict <: first index wins
    }

    float4 q0 = s_cb[2 * bi], q1 = s_cb[2 * bi + 1];
    float4 o0 = make_float4(q0.x * scale, q0.y * scale, q0.z * scale, q0.w * scale);
    float4 o1 = make_float4(q1.x * scale, q1.y * scale, q1.z * scale, q1.w * scale);
    float4* out4 = reinterpret_cast<float4*>(g_wq);
    out4[2 * g]     = o0;
    out4[2 * g + 1] = o1;
}

// ---------------------------------------------------------------------------
// Kernel 2: fp32 SGEMM, C[m,n] = sum_k A[m,k] * B[n,k] + bias[n]
// A = x [M,K] row-major, B = g_wq [N,K] row-major (TN layout, both K-major).
// Tiles: BM=BN=128, BK=16; 256 threads; 8x8 register micro-tile per thread.
// Double-buffered SMEM with register prefetch.
// ---------------------------------------------------------------------------
#define BM 128
#define BN 128
#define BK 16
#define TM 8
#define TN 8

__global__ __launch_bounds__(256, 2)
void sgemm_tn_bias(const float* __restrict__ A,
                   const float* __restrict__ bias,
                   float* __restrict__ C) {
    const int M = MDIM, N = ODIM, K = IDIM;
    const float* B = g_wq;

    __shared__ float sA[2][BK][BM];
    __shared__ float sB[2][BK][BN];

    const int tid = threadIdx.x;
    const int bm = blockIdx.y * BM;
    const int bn = blockIdx.x * BN;

    // Global-load mapping: 512 float4 per operand tile -> 2 per thread.
    const int lr = tid >> 2;            // 0..63  (row within first 64)
    const int lk = (tid & 3) << 2;      // k offset: 0,4,8,12
    const float* Aptr = A + (size_t)(bm + lr) * K + lk;
    const float* Bptr = B + (size_t)(bn + lr) * K + lk;

    float4 pa0, pa1, pb0, pb1;
    pa0 = *reinterpret_cast<const float4*>(Aptr);
    pa1 = *reinterpret_cast<const float4*>(Aptr + (size_t)64 * K);
    pb0 = *reinterpret_cast<const float4*>(Bptr);
    pb1 = *reinterpret_cast<const float4*>(Bptr + (size_t)64 * K);

#define STS_TILE(buf)                                                        \
    do {                                                                     \
        sA[buf][lk + 0][lr]      = pa0.x; sA[buf][lk + 1][lr]      = pa0.y;  \
        sA[buf][lk + 2][lr]      = pa0.z; sA[buf][lk + 3][lr]      = pa0.w;  \
        sA[buf][lk + 0][lr + 64] = pa1.x; sA[buf][lk + 1][lr + 64] = pa1.y;  \
        sA[buf][lk + 2][lr + 64] = pa1.z; sA[buf][lk + 3][lr + 64] = pa1.w;  \
        sB[buf][lk + 0][lr]      = pb0.x; sB[buf][lk + 1][lr]      = pb0.y;  \
        sB[buf][lk + 2][lr]      = pb0.z; sB[buf][lk + 3][lr]      = pb0.w;  \
        sB[buf][lk + 0][lr + 64] = pb1.x; sB[buf][lk + 1][lr + 64] = pb1.y;  \
        sB[buf][lk + 2][lr + 64] = pb1.z; sB[buf][lk + 3][lr + 64] = pb1.w;  \
    } while (0)

    STS_TILE(0);
    __syncthreads();

    const int ty = tid >> 4;   // 0..15 -> m micro-tile
    const int tx = tid & 15;   // 0..15 -> n micro-tile

    float acc[TM][TN];
#pragma unroll
    for (int i = 0; i < TM; ++i)
#pragma unroll
        for (int j = 0; j < TN; ++j) acc[i][j] = 0.0f;

    const int nt = K / BK;     // 128 k-tiles
    for (int t = 0; t < nt; ++t) {
        const int cur = t & 1;
        if (t + 1 < nt) {
            const float* Ap = Aptr + (size_t)(t + 1) * BK;
            const float* Bp = Bptr + (size_t)(t + 1) * BK;
            pa0 = *reinterpret_cast<const float4*>(Ap);
            pa1 = *reinterpret_cast<const float4*>(Ap + (size_t)64 * K);
            pb0 = *reinterpret_cast<const float4*>(Bp);
            pb1 = *reinterpret_cast<const float4*>(Bp + (size_t)64 * K);
        }

#pragma unroll
        for (int k = 0; k < BK; ++k) {
            float4 a0 = *reinterpret_cast<const float4*>(&sA[cur][k][ty * TM]);
            float4 a1 = *reinterpret_cast<const float4*>(&sA[cur][k][ty * TM + 4]);
            float4 b0 = *reinterpret_cast<const float4*>(&sB[cur][k][tx * TN]);
            float4 b1 = *reinterpret_cast<const float4*>(&sB[cur][k][tx * TN + 4]);
            float ar[TM] = {a0.x, a0.y, a0.z, a0.w, a1.x, a1.y, a1.z, a1.w};
            float br[TN] = {b0.x, b0.y, b0.z, b0.w, b1.x, b1.y, b1.z, b1.w};
#pragma unroll
            for (int i = 0; i < TM; ++i)
#pragma unroll
                for (int j = 0; j < TN; ++j)
                    acc[i][j] = fmaf(ar[i], br[j], acc[i][j]);
        }

        if (t + 1 < nt) {
            __syncthreads();           // all reads of buf cur^1 (iter t-1) done
            STS_TILE(cur ^ 1);
            __syncthreads();           // stores visible before next compute
        }
    }

    // Epilogue: add bias, vectorized stores.
    float bv[TN];
#pragma unroll
    for (int j = 0; j < TN; ++j) bv[j] = bias[bn + tx * TN + j];

#pragma unroll
    for (int i = 0; i < TM; ++i) {
        const int m = bm + ty * TM + i;
        float* Crow = C + (size_t)m * N + bn + tx * TN;
        float4 r0 = make_float4(acc[i][0] + bv[0], acc[i][1] + bv[1],
                                acc[i][2] + bv[2], acc[i][3] + bv[3]);
        float4 r1 = make_float4(acc[i][4] + bv[4], acc[i][5] + bv[5],
                                acc[i][6] + bv[6], acc[i][7] + bv[7]);
        reinterpret_cast<float4*>(Crow)[0] = r0;
        reinterpret_cast<float4*>(Crow)[1] = r1;
    }
#undef STS_TILE
}

// ---------------------------------------------------------------------------
// Launch: quantize, then GEMM (same stream => ordered). Graph-capturable:
// kernel launches only, no allocs, no syncs.
// ---------------------------------------------------------------------------
extern "C" void kernel_launch(void* const* d_in, const int* in_sizes, int n_in,
                              void* d_out, int out_size) {
    const float* x    = (const float*)d_in[0];   // [4,1024,2048]
    const float* w    = (const float*)d_in[1];   // [2048,2048]
    const float* cb   = (const float*)d_in[2];   // [256,8]
    const float* rs   = (const float*)d_in[3];   // [2048,1]
    const float* bias = (const float*)d_in[4];   // [2048]
    float* out = (float*)d_out;                  // [4,1024,2048]

    pq_quant_kernel<<<NGROUPS / 256, 256>>>(w, cb, rs);

    dim3 grid(ODIM / BN, MDIM / BM);             // (16, 32) = 512 blocks
    sgemm_tn_bias<<<grid, 256>>>(x, bias, out);
}

// round 7
// speedup vs baseline: 2.3818x; 2.3818x over previous
#include <cuda_runtime.h>
#include <cuda_bf16.h>
#include <cstdint>

// ===========================================================================
// PQLinear: out = x @ wq.T + bias (wq = PQ-dequantized weight).
//  K1: pq_quant  -> split-bf16 weight (wh, wl)   [argmin math identical to R5]
//  K2: xsplit    -> split-bf16 activation (xh, xl)
//  K3: one mma.sync bf16 GEMM with K' = 3*2048 (xh*wh + xh*wl + xl*wh),
//      5-stage cp.async pipeline, swizzled smem, ldmatrix fragments.
// All PTX used here is plain sm_80+ (assembles under .target sm_103).
// ===========================================================================

#define ODIM 2048
#define IDIM 2048
#define MDIM 4096
#define KCB  256
#define NGROUPS ((ODIM * IDIM) / 8)     // 524288
#define GPR_SHIFT 8                     // groups per weight row

__device__ __align__(16) __nv_bfloat16 g_wh[ODIM * IDIM];
__device__ __align__(16) __nv_bfloat16 g_wl[ODIM * IDIM];
__device__ __align__(16) __nv_bfloat16 g_xh[MDIM * IDIM];
__device__ __align__(16) __nv_bfloat16 g_xl[MDIM * IDIM];

// ===========================================================================
// Kernel 1: PQ quantize. Distance/argmin math byte-identical to the R5
// passing kernel (rel_err 8.5e-7 => zero assignment flips). Emits bf16 hi/lo.
// ===========================================================================
__global__ __launch_bounds__(256)
void pq_quant_kernel(const float* __restrict__ w,
                     const float* __restrict__ cb,
                     const float* __restrict__ rs) {
    __shared__ float4 s_cb[KCB * 2];
    __shared__ float  s_cn[KCB];

    const int tid = threadIdx.x;
    const float4* cb4 = reinterpret_cast<const float4*>(cb);
    for (int i = tid; i < KCB * 2; i += 256) s_cb[i] = cb4[i];
    __syncthreads();
    for (int i = tid; i < KCB; i += 256) {
        float4 a = s_cb[2 * i], b = s_cb[2 * i + 1];
        s_cn[i] = a.x * a.x + a.y * a.y + a.z * a.z + a.w * a.w +
                  b.x * b.x + b.y * b.y + b.z * b.z + b.w * b.w;
    }
    __syncthreads();

    const int g = blockIdx.x * 256 + tid;
    const int row = g >> GPR_SHIFT;
    const float scale = rs[row];

    const float4* w4 = reinterpret_cast<const float4*>(w);
    float4 w0 = w4[2 * g], w1 = w4[2 * g + 1];
    float gv0 = w0.x / scale, gv1 = w0.y / scale, gv2 = w0.z / scale, gv3 = w0.w / scale;
    float gv4 = w1.x / scale, gv5 = w1.y / scale, gv6 = w1.z / scale, gv7 = w1.w / scale;

    float best = 3.402823466e38f;
    int bi = 0;
#pragma unroll 8
    for (int k = 0; k < KCB; ++k) {
        float4 c0 = s_cb[2 * k], c1 = s_cb[2 * k + 1];
        float dot = gv0 * c0.x;
        dot = fmaf(gv1, c0.y, dot);
        dot = fmaf(gv2, c0.z, dot);
        dot = fmaf(gv3, c0.w, dot);
        dot = fmaf(gv4, c1.x, dot);
        dot = fmaf(gv5, c1.y, dot);
        dot = fmaf(gv6, c1.z, dot);
        dot = fmaf(gv7, c1.w, dot);
        float d = fmaf(-2.0f, dot, s_cn[k]);
        if (d < best) { best = d; bi = k; }       // strict <: first index wins
    }

    float4 q0 = s_cb[2 * bi], q1 = s_cb[2 * bi + 1];
    float vals[8] = {q0.x * scale, q0.y * scale, q0.z * scale, q0.w * scale,
                     q1.x * scale, q1.y * scale, q1.z * scale, q1.w * scale};

    union B8 { __nv_bfloat16 b[8]; uint4 u; } hh, ll;
#pragma unroll
    for (int j = 0; j < 8; ++j) {
        __nv_bfloat16 h = __float2bfloat16(vals[j]);
        hh.b[j] = h;
        ll.b[j] = __float2bfloat16(vals[j] - __bfloat162float(h));
    }
    reinterpret_cast<uint4*>(g_wh)[g] = hh.u;
    reinterpret_cast<uint4*>(g_wl)[g] = ll.u;
}

// ===========================================================================
// Kernel 2: split x into bf16 hi/lo.
// ===========================================================================
__global__ __launch_bounds__(256)
void xsplit_kernel(const float* __restrict__ x) {
    const int i = blockIdx.x * 256 + threadIdx.x;     // float4 index
    float4 v = reinterpret_cast<const float4*>(x)[i];
    float vs[4] = {v.x, v.y, v.z, v.w};
    union B4 { __nv_bfloat16 b[4]; uint2 u; } hh, ll;
#pragma unroll
    for (int j = 0; j < 4; ++j) {
        __nv_bfloat16 h = __float2bfloat16(vs[j]);
        hh.b[j] = h;
        ll.b[j] = __float2bfloat16(vs[j] - __bfloat162float(h));
    }
    reinterpret_cast<uint2*>(g_xh)[i] = hh.u;
    reinterpret_cast<uint2*>(g_xl)[i] = ll.u;
}

// ===========================================================================
// Kernel 3: bf16 mma.sync GEMM. C[m,n] = sum_k' A'[m,k']*B'[n,k'] + bias[n]
//   k' in [0,2048): xh * wh ; [2048,4096): xh * wl ; [4096,6144): xl * wh
// BM=BN=128, BK=32, 256 threads, warp tile 64x32, 5-stage cp.async pipeline.
// ===========================================================================
#define BM 128
#define BN 128
#define BK 32
#define NST 5
#define KTOT 192                       // 3 * (2048/32)
#define TILE_A_BYTES (BM * 64)         // 8 KB (64 bytes per row)
#define TILE_B_BYTES (BN * 64)
#define STAGE_BYTES (TILE_A_BYTES + TILE_B_BYTES)   // 16 KB
#define GEMM_SMEM (NST * STAGE_BYTES)               // 80 KB

__device__ __forceinline__ uint32_t smem_u32(const void* p) {
    uint32_t a;
    asm("{ .reg .u64 t; cvta.to.shared.u64 t, %1; cvt.u32.u64 %0, t; }"
        : "=r"(a) : "l"(p));
    return a;
}
// Swizzle: 16B granule g (0..3) within 64B row -> g ^ ((row>>1)&3).
// Makes cp.async stores and every 8-address ldmatrix phase conflict-free.
__device__ __forceinline__ uint32_t sw_off(int row, int g) {
    return (uint32_t)(row * 64 + ((g ^ ((row >> 1) & 3)) << 4));
}
__device__ __forceinline__ void cp16(uint32_t s, const void* gp) {
    asm volatile("cp.async.cg.shared.global [%0], [%1], 16;"
                 :: "r"(s), "l"(gp) : "memory");
}
__device__ __forceinline__ void ldm4(uint32_t* r, uint32_t a) {
    asm volatile("ldmatrix.sync.aligned.m8n8.x4.shared.b16 {%0,%1,%2,%3}, [%4];"
                 : "=r"(r[0]), "=r"(r[1]), "=r"(r[2]), "=r"(r[3]) : "r"(a));
}
__device__ __forceinline__ void mma16816(float* c, const uint32_t* a,
                                         const uint32_t* b) {
    asm volatile(
        "mma.sync.aligned.m16n8k16.row.col.f32.bf16.bf16.f32 "
        "{%0,%1,%2,%3}, {%4,%5,%6,%7}, {%8,%9}, {%0,%1,%2,%3};"
        : "+f"(c[0]), "+f"(c[1]), "+f"(c[2]), "+f"(c[3])
        : "r"(a[0]), "r"(a[1]), "r"(a[2]), "r"(a[3]), "r"(b[0]), "r"(b[1]));
}

__global__ __launch_bounds__(256, 2)
void gemm_mma(const float* __restrict__ bias, float* __restrict__ C) {
    extern __shared__ char smem[];
    const uint32_t sbase = smem_u32(smem);
    const int tid = threadIdx.x;
    const int bm = blockIdx.y * BM, bn = blockIdx.x * BN;

    // --- cp.async mapping: 256 threads x 16B, rows r0 and r0+64, granule gq
    const int gq = tid & 3, r0 = tid >> 2;          // r0: 0..63

    // --- warp fragment mapping: warp tile 64x32 at (wm*64, wn*32)
    const int wid = tid >> 5, lane = tid & 31;
    const int wm = wid >> 2, wn = wid & 3;
    const int a_row_l = lane & 15;                  // + (kk>>3)+(lane>>4) granule
    const int a_g_l   = lane >> 4;
    const int b_row_l = (lane & 7) + ((lane >> 4) << 3);
    const int b_g_l   = (lane >> 3) & 1;

    float acc[4][4][4];
#pragma unroll
    for (int i = 0; i < 4; ++i)
#pragma unroll
        for (int j = 0; j < 4; ++j)
#pragma unroll
            for (int v = 0; v < 4; ++v) acc[i][j][v] = 0.0f;

    auto load_tile = [&](int slot, int kt) {
        // pass p = kt>>6: A src = xh,xh,xl ; B src = wh,wl,wh
        const __nv_bfloat16* As = (kt < 128) ? g_xh : g_xl;
        const __nv_bfloat16* Bs = ((kt >> 6) == 1) ? g_wl : g_wh;
        const int kb = (kt & 63) * 64;              // byte offset within a row
        const char* ga = (const char*)As + (size_t)(bm + r0) * 4096 + kb + gq * 16;
        const char* gb = (const char*)Bs + (size_t)(bn + r0) * 4096 + kb + gq * 16;
        const uint32_t sa = sbase + slot * STAGE_BYTES;
        const uint32_t sb = sa + TILE_A_BYTES;
        cp16(sa + sw_off(r0,      gq), ga);
        cp16(sa + sw_off(r0 + 64, gq), ga + (size_t)64 * 4096);
        cp16(sb + sw_off(r0,      gq), gb);
        cp16(sb + sw_off(r0 + 64, gq), gb + (size_t)64 * 4096);
    };

    // --- prologue: fill NST-1 stages
#pragma unroll
    for (int s = 0; s < NST - 1; ++s) {
        load_tile(s, s);
        asm volatile("cp.async.commit_group;" ::: "memory");
    }

    // --- main loop
    for (int kt = 0; kt < KTOT; ++kt) {
        asm volatile("cp.async.wait_group %0;" :: "n"(NST - 2) : "memory");
        __syncthreads();

        const int nxt = kt + NST - 1;
        if (nxt < KTOT) load_tile(nxt % NST, nxt);
        asm volatile("cp.async.commit_group;" ::: "memory");

        const uint32_t sa = sbase + (kt % NST) * STAGE_BYTES;
        const uint32_t sb = sa + TILE_A_BYTES;

#pragma unroll
        for (int kk = 0; kk < BK; kk += 16) {
            uint32_t afr[4][4], bfr[2][4];
            const int gA = (kk >> 3) + a_g_l;
#pragma unroll
            for (int mi = 0; mi < 4; ++mi)
                ldm4(afr[mi], sa + sw_off(wm * 64 + mi * 16 + a_row_l, gA));
            const int gB = (kk >> 3) + b_g_l;
#pragma unroll
            for (int nj = 0; nj < 2; ++nj)
                ldm4(bfr[nj], sb + sw_off(wn * 32 + nj * 16 + b_row_l, gB));
#pragma unroll
            for (int mi = 0; mi < 4; ++mi)
#pragma unroll
                for (int ni = 0; ni < 4; ++ni)
                    mma16816(acc[mi][ni], afr[mi], &bfr[ni >> 1][(ni & 1) * 2]);
        }
    }

    // --- epilogue: c-frag layout m16n8: rows lane>>2 / +8, cols (lane&3)*2
#pragma unroll
    for (int mi = 0; mi < 4; ++mi) {
        const int r_lo = bm + wm * 64 + mi * 16 + (lane >> 2);
#pragma unroll
        for (int ni = 0; ni < 4; ++ni) {
            const int c0 = bn + wn * 32 + ni * 8 + (lane & 3) * 2;
            const float b0 = bias[c0], b1 = bias[c0 + 1];
            float2 v0 = make_float2(acc[mi][ni][0] + b0, acc[mi][ni][1] + b1);
            float2 v1 = make_float2(acc[mi][ni][2] + b0, acc[mi][ni][3] + b1);
            *reinterpret_cast<float2*>(C + (size_t)r_lo * ODIM + c0) = v0;
            *reinterpret_cast<float2*>(C + (size_t)(r_lo + 8) * ODIM + c0) = v1;
        }
    }
}

// ===========================================================================
// Host launch: three ordered kernel launches, graph-capturable, no allocs.
// ===========================================================================
extern "C" void kernel_launch(void* const* d_in, const int* in_sizes, int n_in,
                              void* d_out, int out_size) {
    const float* x    = (const float*)d_in[0];   // [4,1024,2048]
    const float* w    = (const float*)d_in[1];   // [2048,2048]
    const float* cb   = (const float*)d_in[2];   // [256,8]
    const float* rs   = (const float*)d_in[3];   // [2048,1]
    const float* bias = (const float*)d_in[4];   // [2048]
    float* out = (float*)d_out;                  // [4,1024,2048]

    pq_quant_kernel<<<NGROUPS / 256, 256>>>(w, cb, rs);
    xsplit_kernel<<<(MDIM * IDIM / 4) / 256, 256>>>(x);

    cudaFuncSetAttribute(gemm_mma,
                         cudaFuncAttributeMaxDynamicSharedMemorySize, GEMM_SMEM);
    dim3 grid(ODIM / BN, MDIM / BM);             // (16, 32) = 512 CTAs
    gemm_mma<<<grid, 256, GEMM_SMEM>>>(bias, out);
}

// round 8
// speedup vs baseline: 2.5596x; 1.0746x over previous
#include <cuda_runtime.h>
#include <cuda_bf16.h>
#include <cstdint>

// ===========================================================================
// PQLinear: out = x @ wq.T + bias (wq = PQ-dequantized weight).
//  K1: pq_quant (f32x2-packed, 2 groups/thread; per-lane math bit-identical
//      to the R5/R7-passing scalar chain) -> split-bf16 weight (wh, wl)
//  K2: xsplit -> split-bf16 activation (xh, xl)
//  K3: one mma.sync bf16 GEMM, K' = 3*2048 (xh*wh + xh*wl + xl*wh),
//      BK=64, 3-stage cp.async pipeline, SW128 swizzle, ldmatrix fragments.
// ===========================================================================

#define ODIM 2048
#define IDIM 2048
#define MDIM 4096
#define KCB  256
#define NGROUPS ((ODIM * IDIM) / 8)     // 524288

__device__ __align__(16) __nv_bfloat16 g_wh[ODIM * IDIM];
__device__ __align__(16) __nv_bfloat16 g_wl[ODIM * IDIM];
__device__ __align__(16) __nv_bfloat16 g_xh[MDIM * IDIM];
__device__ __align__(16) __nv_bfloat16 g_xl[MDIM * IDIM];

// -------------------- f32x2 packed helpers (sm_100+ base PTX) --------------
#define PACK2(out, lo, hi) \
    asm("mov.b64 %0, {%1, %2};" : "=l"(out) : "f"(lo), "f"(hi))
#define UNPACK2(lo, hi, in) \
    asm("mov.b64 {%0, %1}, %2;" : "=f"(lo), "=f"(hi) : "l"(in))
#define MUL2(out, a, b) \
    asm("mul.rn.f32x2 %0, %1, %2;" : "=l"(out) : "l"(a), "l"(b))
#define FMA2(out, a, b, c) \
    asm("fma.rn.f32x2 %0, %1, %2, %3;" : "=l"(out) : "l"(a), "l"(b), "l"(c))

// ===========================================================================
// Kernel 1: PQ quantize, 2 groups per thread via f32x2 lanes.
// Lane arithmetic (mul, 7xfma, fma(-2,dot,cn), strict < first-wins argmin)
// is identical per-lane to the verified scalar kernel.
// ===========================================================================
__global__ __launch_bounds__(256)
void pq_quant_kernel(const float* __restrict__ w,
                     const float* __restrict__ cb,
                     const float* __restrict__ rs) {
    // Lane-duplicated codebook: s_cb2[k*8+j] = (c_kj, c_kj). 16 KB + 2 KB.
    __shared__ float2 s_cb2[KCB * 8];
    __shared__ float2 s_cn2[KCB];

    const int tid = threadIdx.x;
    {   // one codeword per thread (256 == KCB)
        const float4* cb4 = reinterpret_cast<const float4*>(cb);
        float4 a = cb4[2 * tid], b = cb4[2 * tid + 1];
        float2* row = s_cb2 + tid * 8;
        row[0] = make_float2(a.x, a.x); row[1] = make_float2(a.y, a.y);
        row[2] = make_float2(a.z, a.z); row[3] = make_float2(a.w, a.w);
        row[4] = make_float2(b.x, b.x); row[5] = make_float2(b.y, b.y);
        row[6] = make_float2(b.z, b.z); row[7] = make_float2(b.w, b.w);
        float cn = a.x * a.x + a.y * a.y + a.z * a.z + a.w * a.w +
                   b.x * b.x + b.y * b.y + b.z * b.z + b.w * b.w;
        s_cn2[tid] = make_float2(cn, cn);
    }
    __syncthreads();

    const int t = blockIdx.x * 256 + tid;      // handles groups 2t, 2t+1
    const int g0 = 2 * t;
    const int row = g0 >> 8;                   // g0 even, g0+1 same row
    const float scale = rs[row];

    // Load both groups (64 contiguous bytes) and divide by scale.
    const float4* w4 = reinterpret_cast<const float4*>(w);
    float4 a0 = w4[4 * t], a1 = w4[4 * t + 1];
    float4 a2 = w4[4 * t + 2], a3 = w4[4 * t + 3];
    float u[8] = {a0.x / scale, a0.y / scale, a0.z / scale, a0.w / scale,
                  a1.x / scale, a1.y / scale, a1.z / scale, a1.w / scale};
    float v[8] = {a2.x / scale, a2.y / scale, a2.z / scale, a2.w / scale,
                  a3.x / scale, a3.y / scale, a3.z / scale, a3.w / scale};

    unsigned long long pj[8];                  // (g0_j, g1_j) packed
#pragma unroll
    for (int j = 0; j < 8; ++j) PACK2(pj[j], u[j], v[j]);
    unsigned long long neg2;
    PACK2(neg2, -2.0f, -2.0f);

    float best0 = 3.402823466e38f, best1 = 3.402823466e38f;
    int bi0 = 0, bi1 = 0;
    const ulonglong2* cbu = reinterpret_cast<const ulonglong2*>(s_cb2);
    const unsigned long long* cnu =
        reinterpret_cast<const unsigned long long*>(s_cn2);

#pragma unroll 8
    for (int k = 0; k < KCB; ++k) {
        ulonglong2 cA = cbu[4 * k], cB = cbu[4 * k + 1];
        ulonglong2 cC = cbu[4 * k + 2], cD = cbu[4 * k + 3];
        unsigned long long dot2, d2;
        MUL2(dot2, pj[0], cA.x);
        FMA2(dot2, pj[1], cA.y, dot2);
        FMA2(dot2, pj[2], cB.x, dot2);
        FMA2(dot2, pj[3], cB.y, dot2);
        FMA2(dot2, pj[4], cC.x, dot2);
        FMA2(dot2, pj[5], cC.y, dot2);
        FMA2(dot2, pj[6], cD.x, dot2);
        FMA2(dot2, pj[7], cD.y, dot2);
        FMA2(d2, neg2, dot2, cnu[k]);
        float d0, d1;
        UNPACK2(d0, d1, d2);
        if (d0 < best0) { best0 = d0; bi0 = k; }   // strict <: first wins
        if (d1 < best1) { best1 = d1; bi1 = k; }
    }

    // Decode + scale + split to bf16 hi/lo (same output math as R7).
#pragma unroll 2
    for (int gi = 0; gi < 2; ++gi) {
        const int bi = gi ? bi1 : bi0;
        const float2* crow = s_cb2 + bi * 8;
        union B8 { __nv_bfloat16 b[8]; uint4 q; } hh, ll;
#pragma unroll
        for (int j = 0; j < 8; ++j) {
            float val = crow[j].x * scale;
            __nv_bfloat16 h = __float2bfloat16(val);
            hh.b[j] = h;
            ll.b[j] = __float2bfloat16(val - __bfloat162float(h));
        }
        reinterpret_cast<uint4*>(g_wh)[g0 + gi] = hh.q;
        reinterpret_cast<uint4*>(g_wl)[g0 + gi] = ll.q;
    }
}

// ===========================================================================
// Kernel 2: split x into bf16 hi/lo.
// ===========================================================================
__global__ __launch_bounds__(256)
void xsplit_kernel(const float* __restrict__ x) {
    const int i = blockIdx.x * 256 + threadIdx.x;     // float4 index
    float4 v = reinterpret_cast<const float4*>(x)[i];
    float vs[4] = {v.x, v.y, v.z, v.w};
    union B4 { __nv_bfloat16 b[4]; uint2 u; } hh, ll;
#pragma unroll
    for (int j = 0; j < 4; ++j) {
        __nv_bfloat16 h = __float2bfloat16(vs[j]);
        hh.b[j] = h;
        ll.b[j] = __float2bfloat16(vs[j] - __bfloat162float(h));
    }
    reinterpret_cast<uint2*>(g_xh)[i] = hh.u;
    reinterpret_cast<uint2*>(g_xl)[i] = ll.u;
}

// ===========================================================================
// Kernel 3: bf16 mma.sync GEMM. C[m,n] = sum_k' A'[m,k']*B'[n,k'] + bias[n]
//   k' in [0,2048): xh*wh ; [2048,4096): xh*wl ; [4096,6144): xl*wh
// BM=BN=128, BK=64, 256 threads, warp tile 64x32, 3-stage cp.async pipeline.
// ===========================================================================
#define BM 128
#define BN 128
#define BK 64
#define NST 3
#define KTOT 96                        // 3 * (2048/64)
#define TILE_A_BYTES (BM * 128)        // 16 KB (128 bytes per row)
#define TILE_B_BYTES (BN * 128)
#define STAGE_BYTES (TILE_A_BYTES + TILE_B_BYTES)   // 32 KB
#define GEMM_SMEM (NST * STAGE_BYTES)               // 96 KB

__device__ __forceinline__ uint32_t smem_u32(const void* p) {
    uint32_t a;
    asm("{ .reg .u64 t; cvta.to.shared.u64 t, %1; cvt.u32.u64 %0, t; }"
        : "=r"(a) : "l"(p));
    return a;
}
// SW128: 16B granule g (0..7) within 128B row -> g ^ (row & 7).
// Conflict-free for cp.async stores and every 8-row ldmatrix phase.
__device__ __forceinline__ uint32_t sw_off(int row, int g) {
    return (uint32_t)(row * 128 + ((g ^ (row & 7)) << 4));
}
__device__ __forceinline__ void cp16(uint32_t s, const void* gp) {
    asm volatile("cp.async.cg.shared.global [%0], [%1], 16;"
                 :: "r"(s), "l"(gp) : "memory");
}
__device__ __forceinline__ void ldm4(uint32_t* r, uint32_t a) {
    asm volatile("ldmatrix.sync.aligned.m8n8.x4.shared.b16 {%0,%1,%2,%3}, [%4];"
                 : "=r"(r[0]), "=r"(r[1]), "=r"(r[2]), "=r"(r[3]) : "r"(a));
}
__device__ __forceinline__ void mma16816(float* c, const uint32_t* a,
                                         const uint32_t* b) {
    asm volatile(
        "mma.sync.aligned.m16n8k16.row.col.f32.bf16.bf16.f32 "
        "{%0,%1,%2,%3}, {%4,%5,%6,%7}, {%8,%9}, {%0,%1,%2,%3};"
        : "+f"(c[0]), "+f"(c[1]), "+f"(c[2]), "+f"(c[3])
        : "r"(a[0]), "r"(a[1]), "r"(a[2]), "r"(a[3]), "r"(b[0]), "r"(b[1]));
}

__global__ __launch_bounds__(256, 2)
void gemm_mma(const float* __restrict__ bias, float* __restrict__ C) {
    extern __shared__ char smem[];
    const uint32_t sbase = smem_u32(smem);
    const int tid = threadIdx.x;
    const int bm = blockIdx.y * BM, bn = blockIdx.x * BN;

    // cp.async mapping: granule gq (0..7), base row r0 (0..31), 4 rows/oprnd
    const int gq = tid & 7, r0 = tid >> 3;

    // warp fragment mapping: warp tile 64x32 at (wm*64, wn*32)
    const int wid = tid >> 5, lane = tid & 31;
    const int wm = wid >> 2, wn = wid & 3;
    const int a_row_l = lane & 15;
    const int a_g_l   = lane >> 4;
    const int b_row_l = (lane & 7) + ((lane >> 4) << 3);
    const int b_g_l   = (lane >> 3) & 1;

    float acc[4][4][4];
#pragma unroll
    for (int i = 0; i < 4; ++i)
#pragma unroll
        for (int j = 0; j < 4; ++j)
#pragma unroll
            for (int v = 0; v < 4; ++v) acc[i][j][v] = 0.0f;

    auto load_tile = [&](int slot, int kt) {
        // pass p = kt>>5: A src = xh,xh,xl ; B src = wh,wl,wh
        const __nv_bfloat16* As = (kt < 64) ? g_xh : g_xl;
        const __nv_bfloat16* Bs = ((kt >> 5) == 1) ? g_wl : g_wh;
        const int kb = (kt & 31) * 128;              // byte offset in row
        const char* ga = (const char*)As + (size_t)(bm + r0) * 4096 + kb + gq * 16;
        const char* gb = (const char*)Bs + (size_t)(bn + r0) * 4096 + kb + gq * 16;
        const uint32_t sa = sbase + slot * STAGE_BYTES;
        const uint32_t sb = sa + TILE_A_BYTES;
#pragma unroll
        for (int rr = 0; rr < 4; ++rr) {
            cp16(sa + sw_off(r0 + rr * 32, gq), ga + (size_t)(rr * 32) * 4096);
            cp16(sb + sw_off(r0 + rr * 32, gq), gb + (size_t)(rr * 32) * 4096);
        }
    };

    // prologue: fill NST-1 stages
#pragma unroll
    for (int s = 0; s < NST - 1; ++s) {
        load_tile(s, s);
        asm volatile("cp.async.commit_group;" ::: "memory");
    }

    // main loop
    for (int kt = 0; kt < KTOT; ++kt) {
        asm volatile("cp.async.wait_group %0;" :: "n"(NST - 2) : "memory");
        __syncthreads();

        const int nxt = kt + NST - 1;
        if (nxt < KTOT) load_tile(nxt % NST, nxt);
        asm volatile("cp.async.commit_group;" ::: "memory");

        const uint32_t sa = sbase + (kt % NST) * STAGE_BYTES;
        const uint32_t sb = sa + TILE_A_BYTES;

#pragma unroll
        for (int kk = 0; kk < BK; kk += 16) {
            uint32_t afr[4][4], bfr[2][4];
            const int gA = (kk >> 3) + a_g_l;
#pragma unroll
            for (int mi = 0; mi < 4; ++mi)
                ldm4(afr[mi], sa + sw_off(wm * 64 + mi * 16 + a_row_l, gA));
            const int gB = (kk >> 3) + b_g_l;
#pragma unroll
            for (int nj = 0; nj < 2; ++nj)
                ldm4(bfr[nj], sb + sw_off(wn * 32 + nj * 16 + b_row_l, gB));
#pragma unroll
            for (int mi = 0; mi < 4; ++mi)
#pragma unroll
                for (int ni = 0; ni < 4; ++ni)
                    mma16816(acc[mi][ni], afr[mi], &bfr[ni >> 1][(ni & 1) * 2]);
        }
    }

    // epilogue: m16n8 c-frag rows lane>>2 / +8, cols (lane&3)*2
#pragma unroll
    for (int mi = 0; mi < 4; ++mi) {
        const int r_lo = bm + wm * 64 + mi * 16 + (lane >> 2);
#pragma unroll
        for (int ni = 0; ni < 4; ++ni) {
            const int c0 = bn + wn * 32 + ni * 8 + (lane & 3) * 2;
            const float b0 = bias[c0], b1 = bias[c0 + 1];
            float2 v0 = make_float2(acc[mi][ni][0] + b0, acc[mi][ni][1] + b1);
            float2 v1 = make_float2(acc[mi][ni][2] + b0, acc[mi][ni][3] + b1);
            *reinterpret_cast<float2*>(C + (size_t)r_lo * ODIM + c0) = v0;
            *reinterpret_cast<float2*>(C + (size_t)(r_lo + 8) * ODIM + c0) = v1;
        }
    }
}

// ===========================================================================
// Host launch: three ordered kernel launches, graph-capturable, no allocs.
// ===========================================================================
extern "C" void kernel_launch(void* const* d_in, const int* in_sizes, int n_in,
                              void* d_out, int out_size) {
    const float* x    = (const float*)d_in[0];   // [4,1024,2048]
    const float* w    = (const float*)d_in[1];   // [2048,2048]
    const float* cb   = (const float*)d_in[2];   // [256,8]
    const float* rs   = (const float*)d_in[3];   // [2048,1]
    const float* bias = (const float*)d_in[4];   // [2048]
    float* out = (float*)d_out;                  // [4,1024,2048]

    pq_quant_kernel<<<NGROUPS / 2 / 256, 256>>>(w, cb, rs);   // 1024 blocks
    xsplit_kernel<<<(MDIM * IDIM / 4) / 256, 256>>>(x);

    cudaFuncSetAttribute(gemm_mma,
                         cudaFuncAttributeMaxDynamicSharedMemorySize, GEMM_SMEM);
    dim3 grid(ODIM / BN, MDIM / BM);             // (16, 32) = 512 CTAs
    gemm_mma<<<grid, 256, GEMM_SMEM>>>(bias, out);
}

// round 9
// speedup vs baseline: 2.6759x; 1.0454x over previous
#include <cuda_runtime.h>
#include <cuda_bf16.h>
#include <cstdint>

// ===========================================================================
// PQLinear: out = x @ wq.T + bias (wq = PQ-dequantized weight).
//  K1: pq_quant (scalar fp32 argmin, byte-identical to the R5/R7-passing
//      kernel) -> split-bf16 weight (wh, wl)
//  K2: xsplit -> split-bf16 activation (xh, xl)
//  K3: one mma.sync bf16 GEMM, K' = 3*2048 (xh*wh + xh*wl + xl*wh),
//      BM=BN=128, BK=64, 4 warps with 64x64 warp tiles, 3-stage cp.async.
// ===========================================================================

#define ODIM 2048
#define IDIM 2048
#define MDIM 4096
#define KCB  256
#define NGROUPS ((ODIM * IDIM) / 8)     // 524288
#define GPR_SHIFT 8                     // groups per weight row

__device__ __align__(16) __nv_bfloat16 g_wh[ODIM * IDIM];
__device__ __align__(16) __nv_bfloat16 g_wl[ODIM * IDIM];
__device__ __align__(16) __nv_bfloat16 g_xh[MDIM * IDIM];
__device__ __align__(16) __nv_bfloat16 g_xl[MDIM * IDIM];

// ===========================================================================
// Kernel 1: PQ quantize (R7 scalar version, verified: 83us, zero flips).
// ===========================================================================
__global__ __launch_bounds__(256)
void pq_quant_kernel(const float* __restrict__ w,
                     const float* __restrict__ cb,
                     const float* __restrict__ rs) {
    __shared__ float4 s_cb[KCB * 2];
    __shared__ float  s_cn[KCB];

    const int tid = threadIdx.x;
    const float4* cb4 = reinterpret_cast<const float4*>(cb);
    for (int i = tid; i < KCB * 2; i += 256) s_cb[i] = cb4[i];
    __syncthreads();
    for (int i = tid; i < KCB; i += 256) {
        float4 a = s_cb[2 * i], b = s_cb[2 * i + 1];
        s_cn[i] = a.x * a.x + a.y * a.y + a.z * a.z + a.w * a.w +
                  b.x * b.x + b.y * b.y + b.z * b.z + b.w * b.w;
    }
    __syncthreads();

    const int g = blockIdx.x * 256 + tid;
    const int row = g >> GPR_SHIFT;
    const float scale = rs[row];

    const float4* w4 = reinterpret_cast<const float4*>(w);
    float4 w0 = w4[2 * g], w1 = w4[2 * g + 1];
    float gv0 = w0.x / scale, gv1 = w0.y / scale, gv2 = w0.z / scale, gv3 = w0.w / scale;
    float gv4 = w1.x / scale, gv5 = w1.y / scale, gv6 = w1.z / scale, gv7 = w1.w / scale;

    float best = 3.402823466e38f;
    int bi = 0;
#pragma unroll 8
    for (int k = 0; k < KCB; ++k) {
        float4 c0 = s_cb[2 * k], c1 = s_cb[2 * k + 1];
        float dot = gv0 * c0.x;
        dot = fmaf(gv1, c0.y, dot);
        dot = fmaf(gv2, c0.z, dot);
        dot = fmaf(gv3, c0.w, dot);
        dot = fmaf(gv4, c1.x, dot);
        dot = fmaf(gv5, c1.y, dot);
        dot = fmaf(gv6, c1.z, dot);
        dot = fmaf(gv7, c1.w, dot);
        float d = fmaf(-2.0f, dot, s_cn[k]);
        if (d < best) { best = d; bi = k; }       // strict <: first index wins
    }

    float4 q0 = s_cb[2 * bi], q1 = s_cb[2 * bi + 1];
    float vals[8] = {q0.x * scale, q0.y * scale, q0.z * scale, q0.w * scale,
                     q1.x * scale, q1.y * scale, q1.z * scale, q1.w * scale};

    union B8 { __nv_bfloat16 b[8]; uint4 u; } hh, ll;
#pragma unroll
    for (int j = 0; j < 8; ++j) {
        __nv_bfloat16 h = __float2bfloat16(vals[j]);
        hh.b[j] = h;
        ll.b[j] = __float2bfloat16(vals[j] - __bfloat162float(h));
    }
    reinterpret_cast<uint4*>(g_wh)[g] = hh.u;
    reinterpret_cast<uint4*>(g_wl)[g] = ll.u;
}

// ===========================================================================
// Kernel 2: split x into bf16 hi/lo.
// ===========================================================================
__global__ __launch_bounds__(256)
void xsplit_kernel(const float* __restrict__ x) {
    const int i = blockIdx.x * 256 + threadIdx.x;     // float4 index
    float4 v = reinterpret_cast<const float4*>(x)[i];
    float vs[4] = {v.x, v.y, v.z, v.w};
    union B4 { __nv_bfloat16 b[4]; uint2 u; } hh, ll;
#pragma unroll
    for (int j = 0; j < 4; ++j) {
        __nv_bfloat16 h = __float2bfloat16(vs[j]);
        hh.b[j] = h;
        ll.b[j] = __float2bfloat16(vs[j] - __bfloat162float(h));
    }
    reinterpret_cast<uint2*>(g_xh)[i] = hh.u;
    reinterpret_cast<uint2*>(g_xl)[i] = ll.u;
}

// ===========================================================================
// Kernel 3: bf16 mma.sync GEMM. C[m,n] = sum_k' A'[m,k']*B'[n,k'] + bias[n]
//   k' in [0,2048): xh*wh ; [2048,4096): xh*wl ; [4096,6144): xl*wh
// BM=BN=128, BK=64, 128 threads (4 warps), warp tile 64x64, 3-stage pipeline.
// ===========================================================================
#define BM 128
#define BN 128
#define BK 64
#define NST 3
#define KTOT 96                        // 3 * (2048/64)
#define GTHREADS 128
#define TILE_A_BYTES (BM * 128)        // 16 KB (128 bytes per row)
#define TILE_B_BYTES (BN * 128)
#define STAGE_BYTES (TILE_A_BYTES + TILE_B_BYTES)   // 32 KB
#define GEMM_SMEM (NST * STAGE_BYTES)               // 96 KB

__device__ __forceinline__ uint32_t smem_u32(const void* p) {
    uint32_t a;
    asm("{ .reg .u64 t; cvta.to.shared.u64 t, %1; cvt.u32.u64 %0, t; }"
        : "=r"(a) : "l"(p));
    return a;
}
// SW128: 16B granule g (0..7) within 128B row -> g ^ (row & 7).
// Conflict-free for cp.async stores and every 8-row ldmatrix phase.
__device__ __forceinline__ uint32_t sw_off(int row, int g) {
    return (uint32_t)(row * 128 + ((g ^ (row & 7)) << 4));
}
__device__ __forceinline__ void cp16(uint32_t s, const void* gp) {
    asm volatile("cp.async.cg.shared.global [%0], [%1], 16;"
                 :: "r"(s), "l"(gp) : "memory");
}
__device__ __forceinline__ void ldm4(uint32_t* r, uint32_t a) {
    asm volatile("ldmatrix.sync.aligned.m8n8.x4.shared.b16 {%0,%1,%2,%3}, [%4];"
                 : "=r"(r[0]), "=r"(r[1]), "=r"(r[2]), "=r"(r[3]) : "r"(a));
}
__device__ __forceinline__ void mma16816(float* c, const uint32_t* a,
                                         const uint32_t* b) {
    asm volatile(
        "mma.sync.aligned.m16n8k16.row.col.f32.bf16.bf16.f32 "
        "{%0,%1,%2,%3}, {%4,%5,%6,%7}, {%8,%9}, {%0,%1,%2,%3};"
        : "+f"(c[0]), "+f"(c[1]), "+f"(c[2]), "+f"(c[3])
        : "r"(a[0]), "r"(a[1]), "r"(a[2]), "r"(a[3]), "r"(b[0]), "r"(b[1]));
}

__global__ __launch_bounds__(GTHREADS, 2)
void gemm_mma(const float* __restrict__ bias, float* __restrict__ C) {
    extern __shared__ char smem[];
    const uint32_t sbase = smem_u32(smem);
    const int tid = threadIdx.x;
    const int bm = blockIdx.y * BM, bn = blockIdx.x * BN;

    // cp.async mapping: granule gq (0..7), base row r0 (0..15), 8 rows/oprnd
    const int gq = tid & 7, r0 = tid >> 3;

    // warp fragment mapping: 2x2 grid of 64x64 warp tiles
    const int wid = tid >> 5, lane = tid & 31;
    const int wm = wid >> 1, wn = wid & 1;
    const int a_row_l = lane & 15;
    const int a_g_l   = lane >> 4;
    const int b_row_l = (lane & 7) + ((lane >> 4) << 3);
    const int b_g_l   = (lane >> 3) & 1;

    float acc[4][8][4];
#pragma unroll
    for (int i = 0; i < 4; ++i)
#pragma unroll
        for (int j = 0; j < 8; ++j)
#pragma unroll
            for (int v = 0; v < 4; ++v) acc[i][j][v] = 0.0f;

    auto load_tile = [&](int slot, int kt) {
        // pass p = kt>>5: A src = xh,xh,xl ; B src = wh,wl,wh
        const __nv_bfloat16* As = (kt < 64) ? g_xh : g_xl;
        const __nv_bfloat16* Bs = ((kt >> 5) == 1) ? g_wl : g_wh;
        const int kb = (kt & 31) * 128;              // byte offset in row
        const char* ga = (const char*)As + (size_t)(bm + r0) * 4096 + kb + gq * 16;
        const char* gb = (const char*)Bs + (size_t)(bn + r0) * 4096 + kb + gq * 16;
        const uint32_t sa = sbase + slot * STAGE_BYTES;
        const uint32_t sb = sa + TILE_A_BYTES;
#pragma unroll
        for (int rr = 0; rr < 8; ++rr) {
            cp16(sa + sw_off(r0 + rr * 16, gq), ga + (size_t)(rr * 16) * 4096);
            cp16(sb + sw_off(r0 + rr * 16, gq), gb + (size_t)(rr * 16) * 4096);
        }
    };

    // prologue: fill NST-1 stages
#pragma unroll
    for (int s = 0; s < NST - 1; ++s) {
        load_tile(s, s);
        asm volatile("cp.async.commit_group;" ::: "memory");
    }

    // main loop
    for (int kt = 0; kt < KTOT; ++kt) {
        asm volatile("cp.async.wait_group %0;" :: "n"(NST - 2) : "memory");
        __syncthreads();

        const int nxt = kt + NST - 1;
        if (nxt < KTOT) load_tile(nxt % NST, nxt);
        asm volatile("cp.async.commit_group;" ::: "memory");

        const uint32_t sa = sbase + (kt % NST) * STAGE_BYTES;
        const uint32_t sb = sa + TILE_A_BYTES;

#pragma unroll
        for (int kk = 0; kk < BK; kk += 16) {
            uint32_t afr[4][4], bfr[4][4];
            const int gA = (kk >> 3) + a_g_l;
#pragma unroll
            for (int mi = 0; mi < 4; ++mi)
                ldm4(afr[mi], sa + sw_off(wm * 64 + mi * 16 + a_row_l, gA));
            const int gB = (kk >> 3) + b_g_l;
#pragma unroll
            for (int nj = 0; nj < 4; ++nj)
                ldm4(bfr[nj], sb + sw_off(wn * 64 + nj * 16 + b_row_l, gB));
#pragma unroll
            for (int mi = 0; mi < 4; ++mi)
#pragma unroll
                for (int ni = 0; ni < 8; ++ni)
                    mma16816(acc[mi][ni], afr[mi], &bfr[ni >> 1][(ni & 1) * 2]);
        }
    }

    // epilogue: m16n8 c-frag rows lane>>2 / +8, cols (lane&3)*2
#pragma unroll
    for (int mi = 0; mi < 4; ++mi) {
        const int r_lo = bm + wm * 64 + mi * 16 + (lane >> 2);
#pragma unroll
        for (int ni = 0; ni < 8; ++ni) {
            const int c0 = bn + wn * 64 + ni * 8 + (lane & 3) * 2;
            const float b0 = bias[c0], b1 = bias[c0 + 1];
            float2 v0 = make_float2(acc[mi][ni][0] + b0, acc[mi][ni][1] + b1);
            float2 v1 = make_float2(acc[mi][ni][2] + b0, acc[mi][ni][3] + b1);
            *reinterpret_cast<float2*>(C + (size_t)r_lo * ODIM + c0) = v0;
            *reinterpret_cast<float2*>(C + (size_t)(r_lo + 8) * ODIM + c0) = v1;
        }
    }
}

// ===========================================================================
// Host launch: three ordered kernel launches, graph-capturable, no allocs.
// ===========================================================================
extern "C" void kernel_launch(void* const* d_in, const int* in_sizes, int n_in,
                              void* d_out, int out_size) {
    const float* x    = (const float*)d_in[0];   // [4,1024,2048]
    const float* w    = (const float*)d_in[1];   // [2048,2048]
    const float* cb   = (const float*)d_in[2];   // [256,8]
    const float* rs   = (const float*)d_in[3];   // [2048,1]
    const float* bias = (const float*)d_in[4];   // [2048]
    float* out = (float*)d_out;                  // [4,1024,2048]

    pq_quant_kernel<<<NGROUPS / 256, 256>>>(w, cb, rs);
    xsplit_kernel<<<(MDIM * IDIM / 4) / 256, 256>>>(x);

    cudaFuncSetAttribute(gemm_mma,
                         cudaFuncAttributeMaxDynamicSharedMemorySize, GEMM_SMEM);
    dim3 grid(ODIM / BN, MDIM / BM);             // (16, 32) = 512 CTAs
    gemm_mma<<<grid, GTHREADS, GEMM_SMEM>>>(bias, out);
}